// round 3
// baseline (speedup 1.0000x reference)
#include <cuda_runtime.h>
#include <math.h>

// ---------------- dims ----------------
#define LL   2048
#define DD   1024
#define II   2048
#define NST  16
#define TSRD 64
#define HQ   16
#define NCH  32
#define CHSZ 64
#define EPSV 1e-6f

// ---------------- scratch ----------------
__device__ float g_proj [LL * 2 * II];
__device__ float g_klin [LL * 512];
__device__ float g_vlin [LL * 512];
__device__ float g_ucl  [LL * II];
__device__ float g_ssm  [LL * 96];
__device__ float g_dtn  [LL * TSRD];
__device__ float g_Bn   [LL * NST];
__device__ float g_Cn   [LL * NST];
__device__ float g_dtact[LL * II];
__device__ float g_chunkh[NCH * II * NST];
__device__ float g_sumdt [NCH * II];
__device__ float g_hstart[NCH * II * NST];
__device__ float g_mamba[LL * II];
__device__ float g_qr   [LL * II];
__device__ float g_kr   [LL * 512];
__device__ float g_attn [LL * II];
__device__ float g_fused[LL * II];

// ---------------- SGEMM 128x128xK, BK=16, double-buffered, 8x8/thread ----------------
// nsplit>1: block z = K-split index, results accumulated via atomicAdd (C pre-zeroed)
__global__ __launch_bounds__(256) void gemm_k(
    const float* __restrict__ A, const float* __restrict__ B, float* __restrict__ C,
    int M, int N, int K, const float* __restrict__ bias, int act, int nsplit)
{
    __shared__ float As[2][16][128];
    __shared__ float Bs[2][16][128];
    const int tid = threadIdx.x;
    const int m0 = blockIdx.y * 128;
    const int n0 = blockIdx.x * 128;
    const int klen = K / nsplit;
    const int ks = blockIdx.z * klen;
    const int nk = klen / 16;

    const int ar  = tid >> 1;
    const int akq = (tid & 1) * 8;
    const int br  = tid >> 4;
    const int bc  = (tid & 15) * 8;
    const bool nfull = (n0 + 128 <= N);

    const float* Ap = A + (size_t)(m0 + ar) * K + ks + akq;
    const float* Bp = B + (size_t)(ks + br) * N;

    // preload tile 0
    {
        float4 a0 = *(const float4*)(Ap);
        float4 a1 = *(const float4*)(Ap + 4);
        As[0][akq + 0][ar] = a0.x; As[0][akq + 1][ar] = a0.y;
        As[0][akq + 2][ar] = a0.z; As[0][akq + 3][ar] = a0.w;
        As[0][akq + 4][ar] = a1.x; As[0][akq + 5][ar] = a1.y;
        As[0][akq + 6][ar] = a1.z; As[0][akq + 7][ar] = a1.w;
        if (nfull) {
            *(float4*)&Bs[0][br][bc]     = *(const float4*)(Bp + n0 + bc);
            *(float4*)&Bs[0][br][bc + 4] = *(const float4*)(Bp + n0 + bc + 4);
        } else {
#pragma unroll
            for (int j = 0; j < 8; j++)
                Bs[0][br][bc + j] = (n0 + bc + j < N) ? Bp[n0 + bc + j] : 0.f;
        }
    }
    __syncthreads();

    const int tr = (tid >> 4) * 8;
    const int tc = (tid & 15) * 8;
    float acc[8][8];
#pragma unroll
    for (int i = 0; i < 8; i++)
#pragma unroll
        for (int j = 0; j < 8; j++) acc[i][j] = 0.f;

    for (int kt = 0; kt < nk; kt++) {
        const int cur = kt & 1, nxt = cur ^ 1;
        float4 a0n, a1n, b0n, b1n;
        float bsc[8];
        const bool have = (kt + 1 < nk);
        if (have) {
            const float* Apn = Ap + (kt + 1) * 16;
            a0n = *(const float4*)(Apn);
            a1n = *(const float4*)(Apn + 4);
            const float* Bpn = Bp + (size_t)(kt + 1) * 16 * N;
            if (nfull) {
                b0n = *(const float4*)(Bpn + n0 + bc);
                b1n = *(const float4*)(Bpn + n0 + bc + 4);
            } else {
#pragma unroll
                for (int j = 0; j < 8; j++)
                    bsc[j] = (n0 + bc + j < N) ? Bpn[n0 + bc + j] : 0.f;
            }
        }

#pragma unroll
        for (int kk = 0; kk < 16; kk++) {
            float a[8], b[8];
            *(float4*)&a[0] = *(const float4*)&As[cur][kk][tr];
            *(float4*)&a[4] = *(const float4*)&As[cur][kk][tr + 4];
            *(float4*)&b[0] = *(const float4*)&Bs[cur][kk][tc];
            *(float4*)&b[4] = *(const float4*)&Bs[cur][kk][tc + 4];
#pragma unroll
            for (int i = 0; i < 8; i++)
#pragma unroll
                for (int j = 0; j < 8; j++) acc[i][j] += a[i] * b[j];
        }

        if (have) {
            As[nxt][akq + 0][ar] = a0n.x; As[nxt][akq + 1][ar] = a0n.y;
            As[nxt][akq + 2][ar] = a0n.z; As[nxt][akq + 3][ar] = a0n.w;
            As[nxt][akq + 4][ar] = a1n.x; As[nxt][akq + 5][ar] = a1n.y;
            As[nxt][akq + 6][ar] = a1n.z; As[nxt][akq + 7][ar] = a1n.w;
            if (nfull) {
                *(float4*)&Bs[nxt][br][bc]     = b0n;
                *(float4*)&Bs[nxt][br][bc + 4] = b1n;
            } else {
#pragma unroll
                for (int j = 0; j < 8; j++) Bs[nxt][br][bc + j] = bsc[j];
            }
        }
        __syncthreads();
    }

#pragma unroll
    for (int i = 0; i < 8; i++) {
        int row = m0 + tr + i;
#pragma unroll
        for (int j = 0; j < 8; j++) {
            int col = n0 + tc + j;
            if (col < N) {
                float v = acc[i][j];
                if (nsplit > 1) {
                    atomicAdd(&C[(size_t)row * N + col], v);
                } else {
                    if (act == 1) {
                        float xx = v + bias[col];
                        v = fmaxf(xx, 0.f) + log1pf(__expf(-fabsf(xx)));
                    }
                    C[(size_t)row * N + col] = v;
                }
            }
        }
    }
}

// ---------------- conv K=4 + SiLU ----------------
__global__ __launch_bounds__(256) void conv_silu_k(
    const float* __restrict__ proj, const float* __restrict__ cw,
    const float* __restrict__ cb, float* __restrict__ ucl)
{
    int idx = blockIdx.x * 256 + threadIdx.x;
    int t = idx >> 11, i = idx & 2047;
    float4 w = *(const float4*)(cw + i * 4);
    float acc = cb[i];
    if (t >= 3) acc += proj[(size_t)(t - 3) * 4096 + i] * w.x;
    if (t >= 2) acc += proj[(size_t)(t - 2) * 4096 + i] * w.y;
    if (t >= 1) acc += proj[(size_t)(t - 1) * 4096 + i] * w.z;
    acc += proj[(size_t)t * 4096 + i] * w.w;
    ucl[idx] = acc / (1.f + __expf(-acc));
}

// ---------------- rmsnorm dt/B/C ----------------
__global__ __launch_bounds__(128) void rmsnorm_dtbc_k(
    const float* __restrict__ ssm, const float* __restrict__ wdt,
    const float* __restrict__ wB, const float* __restrict__ wC,
    float* __restrict__ dtn, float* __restrict__ Bn, float* __restrict__ Cn)
{
    int warp = (blockIdx.x * blockDim.x + threadIdx.x) >> 5;
    int lane = threadIdx.x & 31;
    if (warp >= LL) return;
    const float* row = ssm + (size_t)warp * 96;

    float v0 = row[lane], v1 = row[lane + 32];
    float ss = v0 * v0 + v1 * v1;
#pragma unroll
    for (int o = 16; o; o >>= 1) ss += __shfl_xor_sync(~0u, ss, o);
    float r = rsqrtf(ss / 64.f + EPSV);
    dtn[warp * 64 + lane]      = v0 * r * wdt[lane];
    dtn[warp * 64 + lane + 32] = v1 * r * wdt[lane + 32];

    float b = (lane < 16) ? row[64 + lane] : 0.f;
    float sb = b * b;
#pragma unroll
    for (int o = 16; o; o >>= 1) sb += __shfl_xor_sync(~0u, sb, o);
    float rb = rsqrtf(sb / 16.f + EPSV);
    if (lane < 16) Bn[warp * 16 + lane] = b * rb * wB[lane];

    float c = (lane < 16) ? row[80 + lane] : 0.f;
    float sc = c * c;
#pragma unroll
    for (int o = 16; o; o >>= 1) sc += __shfl_xor_sync(~0u, sc, o);
    float rc = rsqrtf(sc / 16.f + EPSV);
    if (lane < 16) Cn[warp * 16 + lane] = c * rc * wC[lane];
}

// ---------------- scan pass A ----------------
__global__ __launch_bounds__(128) void scan_passA_k(
    const float* __restrict__ dtact, const float* __restrict__ ucl,
    const float* __restrict__ Bn, const float* __restrict__ A_log,
    float* __restrict__ chunkh, float* __restrict__ sumdt)
{
    __shared__ float Bs[CHSZ][NST];
    const int c = blockIdx.y;
    const int i = blockIdx.x * 128 + threadIdx.x;
    for (int idx = threadIdx.x; idx < CHSZ * NST; idx += 128)
        Bs[idx >> 4][idx & 15] = Bn[(size_t)(c * CHSZ + (idx >> 4)) * NST + (idx & 15)];
    __syncthreads();

    float Ai[NST];
#pragma unroll
    for (int n = 0; n < NST; n++) Ai[n] = -__expf(A_log[(size_t)i * NST + n]);
    // geometric structure check: Ai[n] == Ai[0]*(n+1)
    bool geom = true;
#pragma unroll
    for (int n = 1; n < NST; n++) {
        float ex = Ai[0] * (float)(n + 1);
        if (fabsf(Ai[n] - ex) > 1e-3f * fabsf(ex)) geom = false;
    }

    float h[NST];
#pragma unroll
    for (int n = 0; n < NST; n++) h[n] = 0.f;
    float sdt = 0.f;

    if (geom) {
        const float a0 = Ai[0];
        for (int t = 0; t < CHSZ; t++) {
            int tg = c * CHSZ + t;
            float dtv = dtact[(size_t)tg * II + i];
            float uv  = ucl[(size_t)tg * II + i];
            sdt += dtv;
            float du = dtv * uv;
            float e1 = __expf(dtv * a0);
            float p = e1;
#pragma unroll
            for (int n = 0; n < NST; n++) {
                h[n] = h[n] * p + du * Bs[t][n];
                p *= e1;
            }
        }
    } else {
        for (int t = 0; t < CHSZ; t++) {
            int tg = c * CHSZ + t;
            float dtv = dtact[(size_t)tg * II + i];
            float uv  = ucl[(size_t)tg * II + i];
            sdt += dtv;
            float du = dtv * uv;
#pragma unroll
            for (int n = 0; n < NST; n++)
                h[n] = h[n] * __expf(dtv * Ai[n]) + du * Bs[t][n];
        }
    }
#pragma unroll
    for (int n = 0; n < NST; n++)
        chunkh[((size_t)c * II + i) * NST + n] = h[n];
    sumdt[c * II + i] = sdt;
}

// ---------------- scan pass B ----------------
__global__ __launch_bounds__(256) void scan_passB_k(
    const float* __restrict__ chunkh, const float* __restrict__ sumdt,
    const float* __restrict__ A_log, float* __restrict__ hstart)
{
    int idx = blockIdx.x * 256 + threadIdx.x;
    int i = idx >> 4;
    float A = -__expf(A_log[idx]);
    float h = 0.f;
    for (int c = 0; c < NCH; c++) {
        hstart[(size_t)c * (II * NST) + idx] = h;
        h = h * __expf(A * sumdt[c * II + i]) + chunkh[(size_t)c * (II * NST) + idx];
    }
}

// ---------------- scan pass C ----------------
__global__ __launch_bounds__(128) void scan_passC_k(
    const float* __restrict__ dtact, const float* __restrict__ ucl,
    const float* __restrict__ Bn, const float* __restrict__ Cn,
    const float* __restrict__ A_log, const float* __restrict__ hstart,
    const float* __restrict__ Dsk, const float* __restrict__ proj,
    float* __restrict__ mamba)
{
    __shared__ float Bs[CHSZ][NST];
    __shared__ float Cs[CHSZ][NST];
    const int c = blockIdx.y;
    const int i = blockIdx.x * 128 + threadIdx.x;
    for (int idx = threadIdx.x; idx < CHSZ * NST; idx += 128) {
        int t = idx >> 4, n = idx & 15;
        Bs[t][n] = Bn[(size_t)(c * CHSZ + t) * NST + n];
        Cs[t][n] = Cn[(size_t)(c * CHSZ + t) * NST + n];
    }
    __syncthreads();

    float Ai[NST];
#pragma unroll
    for (int n = 0; n < NST; n++) Ai[n] = -__expf(A_log[(size_t)i * NST + n]);
    bool geom = true;
#pragma unroll
    for (int n = 1; n < NST; n++) {
        float ex = Ai[0] * (float)(n + 1);
        if (fabsf(Ai[n] - ex) > 1e-3f * fabsf(ex)) geom = false;
    }

    float h[NST];
#pragma unroll
    for (int n = 0; n < NST; n++) h[n] = hstart[((size_t)c * II + i) * NST + n];
    const float Dv = Dsk[i];

    if (geom) {
        const float a0 = Ai[0];
        for (int t = 0; t < CHSZ; t++) {
            int tg = c * CHSZ + t;
            float dtv = dtact[(size_t)tg * II + i];
            float uv  = ucl[(size_t)tg * II + i];
            float du = dtv * uv;
            float e1 = __expf(dtv * a0);
            float p = e1;
            float y = 0.f;
#pragma unroll
            for (int n = 0; n < NST; n++) {
                h[n] = h[n] * p + du * Bs[t][n];
                y += h[n] * Cs[t][n];
                p *= e1;
            }
            float g = proj[(size_t)tg * 4096 + 2048 + i];
            float sg = g / (1.f + __expf(-g));
            mamba[(size_t)tg * II + i] = (y + uv * Dv) * sg;
        }
    } else {
        for (int t = 0; t < CHSZ; t++) {
            int tg = c * CHSZ + t;
            float dtv = dtact[(size_t)tg * II + i];
            float uv  = ucl[(size_t)tg * II + i];
            float du = dtv * uv;
            float y = 0.f;
#pragma unroll
            for (int n = 0; n < NST; n++) {
                h[n] = h[n] * __expf(dtv * Ai[n]) + du * Bs[t][n];
                y += h[n] * Cs[t][n];
            }
            float g = proj[(size_t)tg * 4096 + 2048 + i];
            float sg = g / (1.f + __expf(-g));
            mamba[(size_t)tg * II + i] = (y + uv * Dv) * sg;
        }
    }
}

// ---------------- RoPE ----------------
__global__ __launch_bounds__(256) void rope_q_k(
    const float* __restrict__ proj, float* __restrict__ qr)
{
    int idx = blockIdx.x * 256 + threadIdx.x;
    int t = idx >> 11, col = idx & 2047, d = col & 127;
    int j = d & 63;
    float ang = (float)t * __expf(-(float)j * 0.14391156831212787f);
    float s, c;
    sincosf(ang, &s, &c);
    float x = proj[(size_t)t * 4096 + col];
    float other = (d < 64) ? proj[(size_t)t * 4096 + col + 64]
                           : proj[(size_t)t * 4096 + col - 64];
    qr[idx] = (d < 64) ? (x * c - other * s) : (x * c + other * s);
}

__global__ __launch_bounds__(256) void rope_k_k(
    const float* __restrict__ klin, float* __restrict__ kr)
{
    int idx = blockIdx.x * 256 + threadIdx.x;
    int t = idx >> 9, col = idx & 511, d = col & 127;
    int j = d & 63;
    float ang = (float)t * __expf(-(float)j * 0.14391156831212787f);
    float s, c;
    sincosf(ang, &s, &c);
    float x = klin[(size_t)t * 512 + col];
    float other = (d < 64) ? klin[(size_t)t * 512 + col + 64]
                           : klin[(size_t)t * 512 + col - 64];
    kr[idx] = (d < 64) ? (x * c - other * s) : (x * c + other * s);
}

// ---------------- flash attention ----------------
__global__ __launch_bounds__(256) void attn_k(
    const float* __restrict__ qr, const float* __restrict__ kr,
    const float* __restrict__ vr, float* __restrict__ attn_out)
{
    extern __shared__ float smem[];
    float* Qs = smem;
    float* Ks = Qs + 8192;
    float* Vs = Ks + 8192;
    float* Ps = Vs + 8192;
    __shared__ float m_s[64], l_s[64], al_s[64];

    const int tid = threadIdx.x;
    const int q0 = blockIdx.x * 64;
    const int h = blockIdx.y;
    const int kvh = h >> 2;
    const float scale = 0.08838834764831845f;

    for (int i = tid * 4; i < 8192; i += 1024) {
        int r = i >> 7, d = i & 127;
        float4 q = *(const float4*)(qr + (size_t)(q0 + r) * 2048 + h * 128 + d);
        q.x *= scale; q.y *= scale; q.z *= scale; q.w *= scale;
        *(float4*)&Qs[i] = q;
    }
    if (tid < 64) { m_s[tid] = -1e30f; l_s[tid] = 0.f; al_s[tid] = 1.f; }

    const int sr = (tid >> 4) << 2;
    const int sc = (tid & 15) << 2;
    const int pc = (tid & 15) << 3;
    float O[4][8];
#pragma unroll
    for (int i = 0; i < 4; i++)
#pragma unroll
        for (int j = 0; j < 8; j++) O[i][j] = 0.f;

    __syncthreads();

    int wstart = q0 - 1024; if (wstart < 128) wstart = 128;

    for (int ti = 0; ti < 20; ti++) {
        int k0;
        if (ti < 2) { k0 = ti << 6; }
        else { k0 = wstart + ((ti - 2) << 6); if (k0 > q0) break; }

        for (int i = tid * 4; i < 8192; i += 1024) {
            int r = i >> 7, d = i & 127;
            size_t off = (size_t)(k0 + r) * 512 + kvh * 128 + d;
            *(float4*)&Ks[i] = *(const float4*)(kr + off);
            *(float4*)&Vs[i] = *(const float4*)(vr + off);
        }
        __syncthreads();

        float s[4][4];
#pragma unroll
        for (int i = 0; i < 4; i++)
#pragma unroll
            for (int j = 0; j < 4; j++) s[i][j] = 0.f;

        for (int kk = 0; kk < 128; kk += 4) {
            float4 a[4], b[4];
#pragma unroll
            for (int i = 0; i < 4; i++) a[i] = *(const float4*)&Qs[(sr + i) * 128 + kk];
#pragma unroll
            for (int j = 0; j < 4; j++) b[j] = *(const float4*)&Ks[(sc + j) * 128 + kk];
#pragma unroll
            for (int i = 0; i < 4; i++)
#pragma unroll
                for (int j = 0; j < 4; j++)
                    s[i][j] += a[i].x * b[j].x + a[i].y * b[j].y + a[i].z * b[j].z + a[i].w * b[j].w;
        }

#pragma unroll
        for (int i = 0; i < 4; i++) {
            int qi = q0 + sr + i;
#pragma unroll
            for (int j = 0; j < 4; j++) {
                int ki = k0 + sc + j;
                bool ok = (ki <= qi) && (((qi - ki) <= 1024) || (ki < 128));
                if (!ok) s[i][j] = -1e30f;
            }
        }

        float rmax[4];
#pragma unroll
        for (int i = 0; i < 4; i++)
            rmax[i] = fmaxf(fmaxf(s[i][0], s[i][1]), fmaxf(s[i][2], s[i][3]));
#pragma unroll
        for (int o = 1; o < 16; o <<= 1)
#pragma unroll
            for (int i = 0; i < 4; i++)
                rmax[i] = fmaxf(rmax[i], __shfl_xor_sync(~0u, rmax[i], o));

        float mo[4], mn[4], rs[4];
#pragma unroll
        for (int i = 0; i < 4; i++) {
            mo[i] = m_s[sr + i];
            mn[i] = fmaxf(mo[i], rmax[i]);
            rs[i] = 0.f;
        }
#pragma unroll
        for (int i = 0; i < 4; i++)
#pragma unroll
            for (int j = 0; j < 4; j++) {
                float p = __expf(s[i][j] - mn[i]);
                Ps[(sr + i) * 64 + sc + j] = p;
                rs[i] += p;
            }
#pragma unroll
        for (int o = 1; o < 16; o <<= 1)
#pragma unroll
            for (int i = 0; i < 4; i++)
                rs[i] += __shfl_xor_sync(~0u, rs[i], o);

        if ((tid & 15) == 0) {
#pragma unroll
            for (int i = 0; i < 4; i++) {
                float al = __expf(mo[i] - mn[i]);
                al_s[sr + i] = al;
                l_s[sr + i] = l_s[sr + i] * al + rs[i];
                m_s[sr + i] = mn[i];
            }
        }
        __syncthreads();

        float al[4];
#pragma unroll
        for (int i = 0; i < 4; i++) al[i] = al_s[sr + i];
#pragma unroll
        for (int i = 0; i < 4; i++)
#pragma unroll
            for (int j = 0; j < 8; j++) O[i][j] *= al[i];

        for (int cix = 0; cix < 64; cix++) {
            float4 v0 = *(const float4*)&Vs[cix * 128 + pc];
            float4 v1 = *(const float4*)&Vs[cix * 128 + pc + 4];
            float p0 = Ps[(sr + 0) * 64 + cix];
            float p1 = Ps[(sr + 1) * 64 + cix];
            float p2 = Ps[(sr + 2) * 64 + cix];
            float p3 = Ps[(sr + 3) * 64 + cix];
            O[0][0] += p0 * v0.x; O[0][1] += p0 * v0.y; O[0][2] += p0 * v0.z; O[0][3] += p0 * v0.w;
            O[0][4] += p0 * v1.x; O[0][5] += p0 * v1.y; O[0][6] += p0 * v1.z; O[0][7] += p0 * v1.w;
            O[1][0] += p1 * v0.x; O[1][1] += p1 * v0.y; O[1][2] += p1 * v0.z; O[1][3] += p1 * v0.w;
            O[1][4] += p1 * v1.x; O[1][5] += p1 * v1.y; O[1][6] += p1 * v1.z; O[1][7] += p1 * v1.w;
            O[2][0] += p2 * v0.x; O[2][1] += p2 * v0.y; O[2][2] += p2 * v0.z; O[2][3] += p2 * v0.w;
            O[2][4] += p2 * v1.x; O[2][5] += p2 * v1.y; O[2][6] += p2 * v1.z; O[2][7] += p2 * v1.w;
            O[3][0] += p3 * v0.x; O[3][1] += p3 * v0.y; O[3][2] += p3 * v0.z; O[3][3] += p3 * v0.w;
            O[3][4] += p3 * v1.x; O[3][5] += p3 * v1.y; O[3][6] += p3 * v1.z; O[3][7] += p3 * v1.w;
        }
        __syncthreads();
    }

#pragma unroll
    for (int i = 0; i < 4; i++) {
        float inv = 1.f / l_s[sr + i];
        float4 o0 = make_float4(O[i][0] * inv, O[i][1] * inv, O[i][2] * inv, O[i][3] * inv);
        float4 o1 = make_float4(O[i][4] * inv, O[i][5] * inv, O[i][6] * inv, O[i][7] * inv);
        float* dst = attn_out + (size_t)(q0 + sr + i) * 2048 + h * 128 + pc;
        *(float4*)dst = o0;
        *(float4*)(dst + 4) = o1;
    }
}

// ---------------- fuse norms ----------------
__global__ __launch_bounds__(256) void fuse_norm_k(
    const float* __restrict__ attn, const float* __restrict__ mamba,
    const float* __restrict__ wa, const float* __restrict__ wm,
    float* __restrict__ fused)
{
    __shared__ float sh[18];
    int t = blockIdx.x, tid = threadIdx.x;
    float av[8], mv[8];
    float sa = 0.f, sm = 0.f;
#pragma unroll
    for (int k = 0; k < 8; k++) {
        int col = tid + k * 256;
        av[k] = attn[(size_t)t * II + col];
        mv[k] = mamba[(size_t)t * II + col];
        sa += av[k] * av[k];
        sm += mv[k] * mv[k];
    }
#pragma unroll
    for (int o = 16; o; o >>= 1) {
        sa += __shfl_xor_sync(~0u, sa, o);
        sm += __shfl_xor_sync(~0u, sm, o);
    }
    int w = tid >> 5;
    if ((tid & 31) == 0) { sh[w] = sa; sh[8 + w] = sm; }
    __syncthreads();
    if (tid == 0) {
        float ta = 0.f, tm = 0.f;
        for (int k = 0; k < 8; k++) { ta += sh[k]; tm += sh[8 + k]; }
        sh[16] = ta; sh[17] = tm;
    }
    __syncthreads();
    float ra = rsqrtf(sh[16] / (float)II + EPSV);
    float rm = rsqrtf(sh[17] / (float)II + EPSV);
#pragma unroll
    for (int k = 0; k < 8; k++) {
        int col = tid + k * 256;
        fused[(size_t)t * II + col] = 0.5f * (av[k] * ra * wa[col] + mv[k] * rm * wm[col]);
    }
}

// ---------------- host ----------------
extern "C" void kernel_launch(void* const* d_in, const int* in_sizes, int n_in,
                              void* d_out, int out_size)
{
    const float* x          = (const float*)d_in[0];
    const float* in_proj_w  = (const float*)d_in[1];
    const float* k_proj_w   = (const float*)d_in[2];
    const float* v_proj_w   = (const float*)d_in[3];
    const float* conv_w     = (const float*)d_in[4];
    const float* conv_b     = (const float*)d_in[5];
    const float* x_proj_w   = (const float*)d_in[6];
    const float* dt_proj_w  = (const float*)d_in[7];
    const float* dt_proj_b  = (const float*)d_in[8];
    const float* A_log      = (const float*)d_in[9];
    const float* D_skip     = (const float*)d_in[10];
    const float* dt_ln_w    = (const float*)d_in[11];
    const float* B_ln_w     = (const float*)d_in[12];
    const float* C_ln_w     = (const float*)d_in[13];
    const float* attn_ln_w  = (const float*)d_in[14];
    const float* mamba_ln_w = (const float*)d_in[15];
    const float* out_proj_w = (const float*)d_in[16];
    float* out = (float*)d_out;

    float *proj, *klin, *vlin, *ucl, *ssm, *dtn, *Bn, *Cn, *dtact;
    float *chunkh, *sumdt, *hstart, *mamba, *qr, *kr, *attn, *fused;
    cudaGetSymbolAddress((void**)&proj,   g_proj);
    cudaGetSymbolAddress((void**)&klin,   g_klin);
    cudaGetSymbolAddress((void**)&vlin,   g_vlin);
    cudaGetSymbolAddress((void**)&ucl,    g_ucl);
    cudaGetSymbolAddress((void**)&ssm,    g_ssm);
    cudaGetSymbolAddress((void**)&dtn,    g_dtn);
    cudaGetSymbolAddress((void**)&Bn,     g_Bn);
    cudaGetSymbolAddress((void**)&Cn,     g_Cn);
    cudaGetSymbolAddress((void**)&dtact,  g_dtact);
    cudaGetSymbolAddress((void**)&chunkh, g_chunkh);
    cudaGetSymbolAddress((void**)&sumdt,  g_sumdt);
    cudaGetSymbolAddress((void**)&hstart, g_hstart);
    cudaGetSymbolAddress((void**)&mamba,  g_mamba);
    cudaGetSymbolAddress((void**)&qr,     g_qr);
    cudaGetSymbolAddress((void**)&kr,     g_kr);
    cudaGetSymbolAddress((void**)&attn,   g_attn);
    cudaGetSymbolAddress((void**)&fused,  g_fused);

    // zero split-K accumulation targets
    cudaMemsetAsync(klin, 0, (size_t)LL * 512 * sizeof(float));
    cudaMemsetAsync(vlin, 0, (size_t)LL * 512 * sizeof(float));
    cudaMemsetAsync(ssm,  0, (size_t)LL * 96 * sizeof(float));
    cudaMemsetAsync(out,  0, (size_t)out_size * sizeof(float));

    // projections
    gemm_k<<<dim3(32, 16, 1), 256>>>(x, in_proj_w, proj, LL, 4096, DD, nullptr, 0, 1);
    gemm_k<<<dim3(4, 16, 4), 256>>>(x, k_proj_w, klin, LL, 512, DD, nullptr, 0, 4);
    gemm_k<<<dim3(4, 16, 4), 256>>>(x, v_proj_w, vlin, LL, 512, DD, nullptr, 0, 4);

    // mamba branch
    conv_silu_k<<<LL * II / 256, 256>>>(proj, conv_w, conv_b, ucl);
    gemm_k<<<dim3(1, 16, 8), 256>>>(ucl, x_proj_w, ssm, LL, 96, II, nullptr, 0, 8);
    rmsnorm_dtbc_k<<<512, 128>>>(ssm, dt_ln_w, B_ln_w, C_ln_w, dtn, Bn, Cn);
    gemm_k<<<dim3(16, 16, 1), 256>>>(dtn, dt_proj_w, dtact, LL, II, TSRD, dt_proj_b, 1, 1);
    scan_passA_k<<<dim3(II / 128, NCH), 128>>>(dtact, ucl, Bn, A_log, chunkh, sumdt);
    scan_passB_k<<<(II * NST) / 256, 256>>>(chunkh, sumdt, A_log, hstart);
    scan_passC_k<<<dim3(II / 128, NCH), 128>>>(dtact, ucl, Bn, Cn, A_log, hstart,
                                               D_skip, proj, mamba);

    // attention branch
    rope_q_k<<<LL * II / 256, 256>>>(proj, qr);
    rope_k_k<<<LL * 512 / 256, 256>>>(klin, kr);
    size_t smem = (size_t)(3 * 8192 + 4096) * sizeof(float);
    cudaFuncSetAttribute(attn_k, cudaFuncAttributeMaxDynamicSharedMemorySize, (int)smem);
    attn_k<<<dim3(LL / 64, HQ), 256, smem>>>(qr, kr, vlin, attn);

    // fuse + out projection (split-K=2, accumulated into zeroed d_out)
    fuse_norm_k<<<LL, 256>>>(attn, mamba, attn_ln_w, mamba_ln_w, fused);
    gemm_k<<<dim3(8, 16, 2), 256>>>(fused, out_proj_w, out, LL, DD, II, nullptr, 0, 2);
}

// round 7
// speedup vs baseline: 1.5506x; 1.5506x over previous
#include <cuda_runtime.h>
#include <math.h>

// ---------------- dims ----------------
#define LL   2048
#define DD   1024
#define II   2048
#define NST  16
#define TSRD 64
#define HQ   16
#define NCH  32
#define CHSZ 64
#define EPSV 1e-6f

// ---------------- scratch ----------------
__device__ float g_proj [LL * 2 * II];
__device__ float g_klin [LL * 512];
__device__ float g_vlin [LL * 512];
__device__ float g_ucl  [LL * II];
__device__ float g_ssm  [LL * 96];
__device__ float g_dtn  [LL * TSRD];
__device__ float g_Bn   [LL * NST];
__device__ float g_Cn   [LL * NST];
__device__ float g_dtact[LL * II];
__device__ float g_chunkh[NCH * II * NST];
__device__ float g_sumdt [NCH * II];
__device__ float g_hstart[NCH * II * NST];
__device__ float g_mamba[LL * II];
__device__ float g_qr   [LL * II];
__device__ float g_kr   [LL * 512];
__device__ float g_attn [LL * II];
__device__ float g_fused[LL * II];

// ---------------- SGEMM: 128x128x8 tiles, 8x8/thread (R1-proven structure) ----------------
// nsplit>1: blockIdx.z indexes a K-split; partial results atomicAdd'ed (C pre-zeroed).
__global__ __launch_bounds__(256) void gemm_k(
    const float* __restrict__ A, const float* __restrict__ B, float* __restrict__ C,
    int M, int N, int K, const float* __restrict__ bias, int act, int nsplit)
{
    __shared__ float As[8][128];
    __shared__ float Bs[8][128];
    const int tid = threadIdx.x;
    const int m0 = blockIdx.y * 128;
    const int n0 = blockIdx.x * 128;
    const int klen = K / nsplit;
    const int ks = blockIdx.z * klen;
    const int ke = ks + klen;
    const int tr = (tid >> 4) * 8;
    const int tc = (tid & 15) * 8;

    float acc[8][8];
#pragma unroll
    for (int i = 0; i < 8; i++)
#pragma unroll
        for (int j = 0; j < 8; j++) acc[i][j] = 0.f;

    const int la_m = tid >> 1;
    const int la_k = (tid & 1) * 4;
    const int lb_k = tid >> 5;
    const int lb_n = (tid * 4) & 127;

    for (int k0 = ks; k0 < ke; k0 += 8) {
        float4 av = *(const float4*)(A + (size_t)(m0 + la_m) * K + k0 + la_k);
        As[la_k + 0][la_m] = av.x;
        As[la_k + 1][la_m] = av.y;
        As[la_k + 2][la_m] = av.z;
        As[la_k + 3][la_m] = av.w;

        int gn = n0 + lb_n;
        float4 bv;
        if (gn + 3 < N) {
            bv = *(const float4*)(B + (size_t)(k0 + lb_k) * N + gn);
        } else {
            const float* br = B + (size_t)(k0 + lb_k) * N;
            bv.x = (gn + 0 < N) ? br[gn + 0] : 0.f;
            bv.y = (gn + 1 < N) ? br[gn + 1] : 0.f;
            bv.z = (gn + 2 < N) ? br[gn + 2] : 0.f;
            bv.w = (gn + 3 < N) ? br[gn + 3] : 0.f;
        }
        *(float4*)&Bs[lb_k][lb_n] = bv;
        __syncthreads();

#pragma unroll
        for (int kk = 0; kk < 8; kk++) {
            float a[8], b[8];
            *(float4*)&a[0] = *(const float4*)&As[kk][tr];
            *(float4*)&a[4] = *(const float4*)&As[kk][tr + 4];
            *(float4*)&b[0] = *(const float4*)&Bs[kk][tc];
            *(float4*)&b[4] = *(const float4*)&Bs[kk][tc + 4];
#pragma unroll
            for (int i = 0; i < 8; i++)
#pragma unroll
                for (int j = 0; j < 8; j++) acc[i][j] += a[i] * b[j];
        }
        __syncthreads();
    }

#pragma unroll
    for (int i = 0; i < 8; i++) {
        int row = m0 + tr + i;
#pragma unroll
        for (int j = 0; j < 8; j++) {
            int col = n0 + tc + j;
            if (col < N) {
                float v = acc[i][j];
                if (nsplit > 1) {
                    atomicAdd(&C[(size_t)row * N + col], v);
                } else {
                    if (act == 1) {
                        float xx = v + bias[col];
                        v = fmaxf(xx, 0.f) + log1pf(__expf(-fabsf(xx)));
                    }
                    C[(size_t)row * N + col] = v;
                }
            }
        }
    }
}

// ---------------- conv K=4 + SiLU ----------------
__global__ __launch_bounds__(256) void conv_silu_k(
    const float* __restrict__ proj, const float* __restrict__ cw,
    const float* __restrict__ cb, float* __restrict__ ucl)
{
    int idx = blockIdx.x * 256 + threadIdx.x;
    int t = idx >> 11, i = idx & 2047;
    float4 w = *(const float4*)(cw + i * 4);
    float acc = cb[i];
    if (t >= 3) acc += proj[(size_t)(t - 3) * 4096 + i] * w.x;
    if (t >= 2) acc += proj[(size_t)(t - 2) * 4096 + i] * w.y;
    if (t >= 1) acc += proj[(size_t)(t - 1) * 4096 + i] * w.z;
    acc += proj[(size_t)t * 4096 + i] * w.w;
    ucl[idx] = acc / (1.f + __expf(-acc));
}

// ---------------- rmsnorm dt/B/C ----------------
__global__ __launch_bounds__(128) void rmsnorm_dtbc_k(
    const float* __restrict__ ssm, const float* __restrict__ wdt,
    const float* __restrict__ wB, const float* __restrict__ wC,
    float* __restrict__ dtn, float* __restrict__ Bn, float* __restrict__ Cn)
{
    int warp = (blockIdx.x * blockDim.x + threadIdx.x) >> 5;
    int lane = threadIdx.x & 31;
    if (warp >= LL) return;
    const float* row = ssm + (size_t)warp * 96;

    float v0 = row[lane], v1 = row[lane + 32];
    float ss = v0 * v0 + v1 * v1;
#pragma unroll
    for (int o = 16; o; o >>= 1) ss += __shfl_xor_sync(~0u, ss, o);
    float r = rsqrtf(ss / 64.f + EPSV);
    dtn[warp * 64 + lane]      = v0 * r * wdt[lane];
    dtn[warp * 64 + lane + 32] = v1 * r * wdt[lane + 32];

    float b = (lane < 16) ? row[64 + lane] : 0.f;
    float sb = b * b;
#pragma unroll
    for (int o = 16; o; o >>= 1) sb += __shfl_xor_sync(~0u, sb, o);
    float rb = rsqrtf(sb / 16.f + EPSV);
    if (lane < 16) Bn[warp * 16 + lane] = b * rb * wB[lane];

    float c = (lane < 16) ? row[80 + lane] : 0.f;
    float sc = c * c;
#pragma unroll
    for (int o = 16; o; o >>= 1) sc += __shfl_xor_sync(~0u, sc, o);
    float rc = rsqrtf(sc / 16.f + EPSV);
    if (lane < 16) Cn[warp * 16 + lane] = c * rc * wC[lane];
}

// ---------------- scan pass A: per-chunk end state + dt sums ----------------
__global__ __launch_bounds__(128) void scan_passA_k(
    const float* __restrict__ dtact, const float* __restrict__ ucl,
    const float* __restrict__ Bn, const float* __restrict__ A_log,
    float* __restrict__ chunkh, float* __restrict__ sumdt)
{
    __shared__ float Bs[CHSZ][NST];
    const int c = blockIdx.y;
    const int i = blockIdx.x * 128 + threadIdx.x;
    for (int idx = threadIdx.x; idx < CHSZ * NST; idx += 128)
        Bs[idx >> 4][idx & 15] = Bn[(size_t)(c * CHSZ + (idx >> 4)) * NST + (idx & 15)];
    __syncthreads();

    float Ai[NST];
#pragma unroll
    for (int n = 0; n < NST; n++) Ai[n] = -__expf(A_log[(size_t)i * NST + n]);
    bool geom = true;
#pragma unroll
    for (int n = 1; n < NST; n++) {
        float ex = Ai[0] * (float)(n + 1);
        if (fabsf(Ai[n] - ex) > 1e-3f * fabsf(ex)) geom = false;
    }

    float h[NST];
#pragma unroll
    for (int n = 0; n < NST; n++) h[n] = 0.f;
    float sdt = 0.f;

    if (geom) {
        const float a0 = Ai[0];
        for (int t = 0; t < CHSZ; t++) {
            int tg = c * CHSZ + t;
            float dtv = dtact[(size_t)tg * II + i];
            float uv  = ucl[(size_t)tg * II + i];
            sdt += dtv;
            float du = dtv * uv;
            float e1 = __expf(dtv * a0);
            float p = e1;
#pragma unroll
            for (int n = 0; n < NST; n++) {
                h[n] = h[n] * p + du * Bs[t][n];
                p *= e1;
            }
        }
    } else {
        for (int t = 0; t < CHSZ; t++) {
            int tg = c * CHSZ + t;
            float dtv = dtact[(size_t)tg * II + i];
            float uv  = ucl[(size_t)tg * II + i];
            sdt += dtv;
            float du = dtv * uv;
#pragma unroll
            for (int n = 0; n < NST; n++)
                h[n] = h[n] * __expf(dtv * Ai[n]) + du * Bs[t][n];
        }
    }
#pragma unroll
    for (int n = 0; n < NST; n++)
        chunkh[((size_t)c * II + i) * NST + n] = h[n];
    sumdt[c * II + i] = sdt;
}

// ---------------- scan pass B: combine over chunks ----------------
__global__ __launch_bounds__(256) void scan_passB_k(
    const float* __restrict__ chunkh, const float* __restrict__ sumdt,
    const float* __restrict__ A_log, float* __restrict__ hstart)
{
    int idx = blockIdx.x * 256 + threadIdx.x;
    int i = idx >> 4;
    float A = -__expf(A_log[idx]);
    float h = 0.f;
    for (int c = 0; c < NCH; c++) {
        hstart[(size_t)c * (II * NST) + idx] = h;
        h = h * __expf(A * sumdt[c * II + i]) + chunkh[(size_t)c * (II * NST) + idx];
    }
}

// ---------------- scan pass C: replay + emit mamba output ----------------
__global__ __launch_bounds__(128) void scan_passC_k(
    const float* __restrict__ dtact, const float* __restrict__ ucl,
    const float* __restrict__ Bn, const float* __restrict__ Cn,
    const float* __restrict__ A_log, const float* __restrict__ hstart,
    const float* __restrict__ Dsk, const float* __restrict__ proj,
    float* __restrict__ mamba)
{
    __shared__ float Bs[CHSZ][NST];
    __shared__ float Cs[CHSZ][NST];
    const int c = blockIdx.y;
    const int i = blockIdx.x * 128 + threadIdx.x;
    for (int idx = threadIdx.x; idx < CHSZ * NST; idx += 128) {
        int t = idx >> 4, n = idx & 15;
        Bs[t][n] = Bn[(size_t)(c * CHSZ + t) * NST + n];
        Cs[t][n] = Cn[(size_t)(c * CHSZ + t) * NST + n];
    }
    __syncthreads();

    float Ai[NST];
#pragma unroll
    for (int n = 0; n < NST; n++) Ai[n] = -__expf(A_log[(size_t)i * NST + n]);
    bool geom = true;
#pragma unroll
    for (int n = 1; n < NST; n++) {
        float ex = Ai[0] * (float)(n + 1);
        if (fabsf(Ai[n] - ex) > 1e-3f * fabsf(ex)) geom = false;
    }

    float h[NST];
#pragma unroll
    for (int n = 0; n < NST; n++) h[n] = hstart[((size_t)c * II + i) * NST + n];
    const float Dv = Dsk[i];

    if (geom) {
        const float a0 = Ai[0];
        for (int t = 0; t < CHSZ; t++) {
            int tg = c * CHSZ + t;
            float dtv = dtact[(size_t)tg * II + i];
            float uv  = ucl[(size_t)tg * II + i];
            float du = dtv * uv;
            float e1 = __expf(dtv * a0);
            float p = e1;
            float y = 0.f;
#pragma unroll
            for (int n = 0; n < NST; n++) {
                h[n] = h[n] * p + du * Bs[t][n];
                y += h[n] * Cs[t][n];
                p *= e1;
            }
            float g = proj[(size_t)tg * 4096 + 2048 + i];
            float sg = g / (1.f + __expf(-g));
            mamba[(size_t)tg * II + i] = (y + uv * Dv) * sg;
        }
    } else {
        for (int t = 0; t < CHSZ; t++) {
            int tg = c * CHSZ + t;
            float dtv = dtact[(size_t)tg * II + i];
            float uv  = ucl[(size_t)tg * II + i];
            float du = dtv * uv;
            float y = 0.f;
#pragma unroll
            for (int n = 0; n < NST; n++) {
                h[n] = h[n] * __expf(dtv * Ai[n]) + du * Bs[t][n];
                y += h[n] * Cs[t][n];
            }
            float g = proj[(size_t)tg * 4096 + 2048 + i];
            float sg = g / (1.f + __expf(-g));
            mamba[(size_t)tg * II + i] = (y + uv * Dv) * sg;
        }
    }
}

// ---------------- RoPE ----------------
__global__ __launch_bounds__(256) void rope_q_k(
    const float* __restrict__ proj, float* __restrict__ qr)
{
    int idx = blockIdx.x * 256 + threadIdx.x;
    int t = idx >> 11, col = idx & 2047, d = col & 127;
    int j = d & 63;
    float ang = (float)t * __expf(-(float)j * 0.14391156831212787f);
    float s, c;
    sincosf(ang, &s, &c);
    float x = proj[(size_t)t * 4096 + col];
    float other = (d < 64) ? proj[(size_t)t * 4096 + col + 64]
                           : proj[(size_t)t * 4096 + col - 64];
    qr[idx] = (d < 64) ? (x * c - other * s) : (x * c + other * s);
}

__global__ __launch_bounds__(256) void rope_k_k(
    const float* __restrict__ klin, float* __restrict__ kr)
{
    int idx = blockIdx.x * 256 + threadIdx.x;
    int t = idx >> 9, col = idx & 511, d = col & 127;
    int j = d & 63;
    float ang = (float)t * __expf(-(float)j * 0.14391156831212787f);
    float s, c;
    sincosf(ang, &s, &c);
    float x = klin[(size_t)t * 512 + col];
    float other = (d < 64) ? klin[(size_t)t * 512 + col + 64]
                           : klin[(size_t)t * 512 + col - 64];
    kr[idx] = (d < 64) ? (x * c - other * s) : (x * c + other * s);
}

// ---------------- flash attention ----------------
__global__ __launch_bounds__(256) void attn_k(
    const float* __restrict__ qr, const float* __restrict__ kr,
    const float* __restrict__ vr, float* __restrict__ attn_out)
{
    extern __shared__ float smem[];
    float* Qs = smem;
    float* Ks = Qs + 8192;
    float* Vs = Ks + 8192;
    float* Ps = Vs + 8192;
    __shared__ float m_s[64], l_s[64], al_s[64];

    const int tid = threadIdx.x;
    const int q0 = blockIdx.x * 64;
    const int h = blockIdx.y;
    const int kvh = h >> 2;
    const float scale = 0.08838834764831845f;

    for (int i = tid * 4; i < 8192; i += 1024) {
        int r = i >> 7, d = i & 127;
        float4 q = *(const float4*)(qr + (size_t)(q0 + r) * 2048 + h * 128 + d);
        q.x *= scale; q.y *= scale; q.z *= scale; q.w *= scale;
        *(float4*)&Qs[i] = q;
    }
    if (tid < 64) { m_s[tid] = -1e30f; l_s[tid] = 0.f; al_s[tid] = 1.f; }

    const int sr = (tid >> 4) << 2;
    const int sc = (tid & 15) << 2;
    const int pc = (tid & 15) << 3;
    float O[4][8];
#pragma unroll
    for (int i = 0; i < 4; i++)
#pragma unroll
        for (int j = 0; j < 8; j++) O[i][j] = 0.f;

    __syncthreads();

    int wstart = q0 - 1024; if (wstart < 128) wstart = 128;

    for (int ti = 0; ti < 20; ti++) {
        int k0;
        if (ti < 2) { k0 = ti << 6; }
        else { k0 = wstart + ((ti - 2) << 6); if (k0 > q0) break; }

        for (int i = tid * 4; i < 8192; i += 1024) {
            int r = i >> 7, d = i & 127;
            size_t off = (size_t)(k0 + r) * 512 + kvh * 128 + d;
            *(float4*)&Ks[i] = *(const float4*)(kr + off);
            *(float4*)&Vs[i] = *(const float4*)(vr + off);
        }
        __syncthreads();

        float s[4][4];
#pragma unroll
        for (int i = 0; i < 4; i++)
#pragma unroll
            for (int j = 0; j < 4; j++) s[i][j] = 0.f;

        for (int kk = 0; kk < 128; kk += 4) {
            float4 a[4], b[4];
#pragma unroll
            for (int i = 0; i < 4; i++) a[i] = *(const float4*)&Qs[(sr + i) * 128 + kk];
#pragma unroll
            for (int j = 0; j < 4; j++) b[j] = *(const float4*)&Ks[(sc + j) * 128 + kk];
#pragma unroll
            for (int i = 0; i < 4; i++)
#pragma unroll
                for (int j = 0; j < 4; j++)
                    s[i][j] += a[i].x * b[j].x + a[i].y * b[j].y + a[i].z * b[j].z + a[i].w * b[j].w;
        }

#pragma unroll
        for (int i = 0; i < 4; i++) {
            int qi = q0 + sr + i;
#pragma unroll
            for (int j = 0; j < 4; j++) {
                int ki = k0 + sc + j;
                bool ok = (ki <= qi) && (((qi - ki) <= 1024) || (ki < 128));
                if (!ok) s[i][j] = -1e30f;
            }
        }

        float rmax[4];
#pragma unroll
        for (int i = 0; i < 4; i++)
            rmax[i] = fmaxf(fmaxf(s[i][0], s[i][1]), fmaxf(s[i][2], s[i][3]));
#pragma unroll
        for (int o = 1; o < 16; o <<= 1)
#pragma unroll
            for (int i = 0; i < 4; i++)
                rmax[i] = fmaxf(rmax[i], __shfl_xor_sync(~0u, rmax[i], o));

        float mo[4], mn[4], rs[4];
#pragma unroll
        for (int i = 0; i < 4; i++) {
            mo[i] = m_s[sr + i];
            mn[i] = fmaxf(mo[i], rmax[i]);
            rs[i] = 0.f;
        }
#pragma unroll
        for (int i = 0; i < 4; i++)
#pragma unroll
            for (int j = 0; j < 4; j++) {
                float p = __expf(s[i][j] - mn[i]);
                Ps[(sr + i) * 64 + sc + j] = p;
                rs[i] += p;
            }
#pragma unroll
        for (int o = 1; o < 16; o <<= 1)
#pragma unroll
            for (int i = 0; i < 4; i++)
                rs[i] += __shfl_xor_sync(~0u, rs[i], o);

        if ((tid & 15) == 0) {
#pragma unroll
            for (int i = 0; i < 4; i++) {
                float al = __expf(mo[i] - mn[i]);
                al_s[sr + i] = al;
                l_s[sr + i] = l_s[sr + i] * al + rs[i];
                m_s[sr + i] = mn[i];
            }
        }
        __syncthreads();

        float al[4];
#pragma unroll
        for (int i = 0; i < 4; i++) al[i] = al_s[sr + i];
#pragma unroll
        for (int i = 0; i < 4; i++)
#pragma unroll
            for (int j = 0; j < 8; j++) O[i][j] *= al[i];

        for (int cix = 0; cix < 64; cix++) {
            float4 v0 = *(const float4*)&Vs[cix * 128 + pc];
            float4 v1 = *(const float4*)&Vs[cix * 128 + pc + 4];
            float p0 = Ps[(sr + 0) * 64 + cix];
            float p1 = Ps[(sr + 1) * 64 + cix];
            float p2 = Ps[(sr + 2) * 64 + cix];
            float p3 = Ps[(sr + 3) * 64 + cix];
            O[0][0] += p0 * v0.x; O[0][1] += p0 * v0.y; O[0][2] += p0 * v0.z; O[0][3] += p0 * v0.w;
            O[0][4] += p0 * v1.x; O[0][5] += p0 * v1.y; O[0][6] += p0 * v1.z; O[0][7] += p0 * v1.w;
            O[1][0] += p1 * v0.x; O[1][1] += p1 * v0.y; O[1][2] += p1 * v0.z; O[1][3] += p1 * v0.w;
            O[1][4] += p1 * v1.x; O[1][5] += p1 * v1.y; O[1][6] += p1 * v1.z; O[1][7] += p1 * v1.w;
            O[2][0] += p2 * v0.x; O[2][1] += p2 * v0.y; O[2][2] += p2 * v0.z; O[2][3] += p2 * v0.w;
            O[2][4] += p2 * v1.x; O[2][5] += p2 * v1.y; O[2][6] += p2 * v1.z; O[2][7] += p2 * v1.w;
            O[3][0] += p3 * v0.x; O[3][1] += p3 * v0.y; O[3][2] += p3 * v0.z; O[3][3] += p3 * v0.w;
            O[3][4] += p3 * v1.x; O[3][5] += p3 * v1.y; O[3][6] += p3 * v1.z; O[3][7] += p3 * v1.w;
        }
        __syncthreads();
    }

#pragma unroll
    for (int i = 0; i < 4; i++) {
        float inv = 1.f / l_s[sr + i];
        float4 o0 = make_float4(O[i][0] * inv, O[i][1] * inv, O[i][2] * inv, O[i][3] * inv);
        float4 o1 = make_float4(O[i][4] * inv, O[i][5] * inv, O[i][6] * inv, O[i][7] * inv);
        float* dst = attn_out + (size_t)(q0 + sr + i) * 2048 + h * 128 + pc;
        *(float4*)dst = o0;
        *(float4*)(dst + 4) = o1;
    }
}

// ---------------- fuse norms ----------------
__global__ __launch_bounds__(256) void fuse_norm_k(
    const float* __restrict__ attn, const float* __restrict__ mamba,
    const float* __restrict__ wa, const float* __restrict__ wm,
    float* __restrict__ fused)
{
    __shared__ float sh[18];
    int t = blockIdx.x, tid = threadIdx.x;
    float av[8], mv[8];
    float sa = 0.f, sm = 0.f;
#pragma unroll
    for (int k = 0; k < 8; k++) {
        int col = tid + k * 256;
        av[k] = attn[(size_t)t * II + col];
        mv[k] = mamba[(size_t)t * II + col];
        sa += av[k] * av[k];
        sm += mv[k] * mv[k];
    }
#pragma unroll
    for (int o = 16; o; o >>= 1) {
        sa += __shfl_xor_sync(~0u, sa, o);
        sm += __shfl_xor_sync(~0u, sm, o);
    }
    int w = tid >> 5;
    if ((tid & 31) == 0) { sh[w] = sa; sh[8 + w] = sm; }
    __syncthreads();
    if (tid == 0) {
        float ta = 0.f, tm = 0.f;
        for (int k = 0; k < 8; k++) { ta += sh[k]; tm += sh[8 + k]; }
        sh[16] = ta; sh[17] = tm;
    }
    __syncthreads();
    float ra = rsqrtf(sh[16] / (float)II + EPSV);
    float rm = rsqrtf(sh[17] / (float)II + EPSV);
#pragma unroll
    for (int k = 0; k < 8; k++) {
        int col = tid + k * 256;
        fused[(size_t)t * II + col] = 0.5f * (av[k] * ra * wa[col] + mv[k] * rm * wm[col]);
    }
}

// ---------------- host ----------------
extern "C" void kernel_launch(void* const* d_in, const int* in_sizes, int n_in,
                              void* d_out, int out_size)
{
    const float* x          = (const float*)d_in[0];
    const float* in_proj_w  = (const float*)d_in[1];
    const float* k_proj_w   = (const float*)d_in[2];
    const float* v_proj_w   = (const float*)d_in[3];
    const float* conv_w     = (const float*)d_in[4];
    const float* conv_b     = (const float*)d_in[5];
    const float* x_proj_w   = (const float*)d_in[6];
    const float* dt_proj_w  = (const float*)d_in[7];
    const float* dt_proj_b  = (const float*)d_in[8];
    const float* A_log      = (const float*)d_in[9];
    const float* D_skip     = (const float*)d_in[10];
    const float* dt_ln_w    = (const float*)d_in[11];
    const float* B_ln_w     = (const float*)d_in[12];
    const float* C_ln_w     = (const float*)d_in[13];
    const float* attn_ln_w  = (const float*)d_in[14];
    const float* mamba_ln_w = (const float*)d_in[15];
    const float* out_proj_w = (const float*)d_in[16];
    float* out = (float*)d_out;

    float *proj, *klin, *vlin, *ucl, *ssm, *dtn, *Bn, *Cn, *dtact;
    float *chunkh, *sumdt, *hstart, *mamba, *qr, *kr, *attn, *fused;
    cudaGetSymbolAddress((void**)&proj,   g_proj);
    cudaGetSymbolAddress((void**)&klin,   g_klin);
    cudaGetSymbolAddress((void**)&vlin,   g_vlin);
    cudaGetSymbolAddress((void**)&ucl,    g_ucl);
    cudaGetSymbolAddress((void**)&ssm,    g_ssm);
    cudaGetSymbolAddress((void**)&dtn,    g_dtn);
    cudaGetSymbolAddress((void**)&Bn,     g_Bn);
    cudaGetSymbolAddress((void**)&Cn,     g_Cn);
    cudaGetSymbolAddress((void**)&dtact,  g_dtact);
    cudaGetSymbolAddress((void**)&chunkh, g_chunkh);
    cudaGetSymbolAddress((void**)&sumdt,  g_sumdt);
    cudaGetSymbolAddress((void**)&hstart, g_hstart);
    cudaGetSymbolAddress((void**)&mamba,  g_mamba);
    cudaGetSymbolAddress((void**)&qr,     g_qr);
    cudaGetSymbolAddress((void**)&kr,     g_kr);
    cudaGetSymbolAddress((void**)&attn,   g_attn);
    cudaGetSymbolAddress((void**)&fused,  g_fused);

    // zero split-K accumulation targets
    cudaMemsetAsync(klin, 0, (size_t)LL * 512 * sizeof(float));
    cudaMemsetAsync(vlin, 0, (size_t)LL * 512 * sizeof(float));
    cudaMemsetAsync(ssm,  0, (size_t)LL * 96 * sizeof(float));

    // projections
    gemm_k<<<dim3(32, 16, 1), 256>>>(x, in_proj_w, proj, LL, 4096, DD, nullptr, 0, 1);
    gemm_k<<<dim3(4, 16, 4), 256>>>(x, k_proj_w, klin, LL, 512, DD, nullptr, 0, 4);
    gemm_k<<<dim3(4, 16, 4), 256>>>(x, v_proj_w, vlin, LL, 512, DD, nullptr, 0, 4);

    // mamba branch
    conv_silu_k<<<LL * II / 256, 256>>>(proj, conv_w, conv_b, ucl);
    gemm_k<<<dim3(1, 16, 8), 256>>>(ucl, x_proj_w, ssm, LL, 96, II, nullptr, 0, 8);
    rmsnorm_dtbc_k<<<512, 128>>>(ssm, dt_ln_w, B_ln_w, C_ln_w, dtn, Bn, Cn);
    gemm_k<<<dim3(16, 16, 1), 256>>>(dtn, dt_proj_w, dtact, LL, II, TSRD, dt_proj_b, 1, 1);
    scan_passA_k<<<dim3(II / 128, NCH), 128>>>(dtact, ucl, Bn, A_log, chunkh, sumdt);
    scan_passB_k<<<(II * NST) / 256, 256>>>(chunkh, sumdt, A_log, hstart);
    scan_passC_k<<<dim3(II / 128, NCH), 128>>>(dtact, ucl, Bn, Cn, A_log, hstart,
                                               D_skip, proj, mamba);

    // attention branch
    rope_q_k<<<LL * II / 256, 256>>>(proj, qr);
    rope_k_k<<<LL * 512 / 256, 256>>>(klin, kr);
    size_t smem = (size_t)(3 * 8192 + 4096) * sizeof(float);
    cudaFuncSetAttribute(attn_k, cudaFuncAttributeMaxDynamicSharedMemorySize, (int)smem);
    attn_k<<<dim3(LL / 64, HQ), 256, smem>>>(qr, kr, vlin, attn);

    // fuse + out projection
    fuse_norm_k<<<LL, 256>>>(attn, mamba, attn_ln_w, mamba_ln_w, fused);
    gemm_k<<<dim3(8, 16, 1), 256>>>(fused, out_proj_w, out, LL, DD, II, nullptr, 0, 1);
}